// round 7
// baseline (speedup 1.0000x reference)
#include <cuda_runtime.h>
#include <math.h>

#define BATCH 16
#define CCH   512
#define NTOK  3136
#define DD    512
#define TDOUT 256
#define MTOT  (BATCH*NTOK)     // 50176
#define NBLK64 (MTOT/64)       // 784
#define L2EPS 1e-12f

// ---------------- scratch (device globals; no runtime allocation) ------------
__device__ float g_QK[(size_t)MTOT * 1024];  // per token: [0:512)=Q, [512:1024)=K (pre-norm then normalized in place)
__device__ float g_Gpart[NBLK64 * 512];      // per-block partial of sum_n qg_n * Q_n
__device__ float g_sspart[NBLK64];           // per-block partial of sum qg^2
__device__ float g_dyn[MTOT];                // gating logits
__device__ float g_w[MTOT];                  // softmax weights
__device__ float g_G[BATCH * DD];            // global query (already scaled by 1/||qg||)

__device__ __forceinline__ float gelu_f(float x) {
    // exact GELU (approximate=False)
    return 0.5f * x * (1.0f + erff(x * 0.70710678118654752440f));
}

// ---------------- kernel 1: [Q|K] = xt @ [wq|wk] + [bq|bk] -------------------
// A is x in [b, c, n] layout -> xt[m=(b,n), c] = x[b*C*N + c*N + n]
// 128x128x8 fp32 tile, 256 threads, 8x8 per thread.
__global__ __launch_bounds__(256) void k_gemm_qk(
    const float* __restrict__ x,
    const float* __restrict__ wq, const float* __restrict__ bq,
    const float* __restrict__ wk, const float* __restrict__ bk)
{
    __shared__ float As[8][128];
    __shared__ float Bs[8][128];
    const int tid = threadIdx.x;
    const int m0 = blockIdx.x * 128;
    const int J0 = blockIdx.y * 128;          // 0..1023

    const float* wmat; const float* bias; int j0;
    if (J0 < 512) { wmat = wq; bias = bq; j0 = J0; }
    else          { wmat = wk; bias = bk; j0 = J0 - 512; }

    // A loads: each thread owns one fixed row of the tile
    const int a_m  = tid & 127;
    const int a_k0 = tid >> 7;                // 0/1, k = a_k0 + 2*i
    const int gm = m0 + a_m;
    const int b_idx = gm / NTOK;
    const int n_idx = gm - b_idx * NTOK;
    const float* xrow = x + (size_t)b_idx * CCH * NTOK + n_idx;

    // B loads: each thread owns one fixed column
    const int bj  = tid & 127;
    const int bk0 = tid >> 7;

    float acc[8][8];
#pragma unroll
    for (int i = 0; i < 8; i++)
#pragma unroll
        for (int j = 0; j < 8; j++) acc[i][j] = 0.f;

    const int rg = (tid >> 4) * 8;
    const int cg = (tid & 15) * 8;

    for (int kt = 0; kt < CCH; kt += 8) {
#pragma unroll
        for (int i = 0; i < 4; i++) {
            int k = a_k0 + 2 * i;
            As[k][a_m] = xrow[(size_t)(kt + k) * NTOK];
        }
#pragma unroll
        for (int i = 0; i < 4; i++) {
            int k = bk0 + 2 * i;
            Bs[k][bj] = wmat[(size_t)(kt + k) * 512 + j0 + bj];
        }
        __syncthreads();
#pragma unroll
        for (int k = 0; k < 8; k++) {
            float a[8], bb[8];
#pragma unroll
            for (int i = 0; i < 8; i++) a[i] = As[k][rg + i];
#pragma unroll
            for (int j = 0; j < 8; j++) bb[j] = Bs[k][cg + j];
#pragma unroll
            for (int i = 0; i < 8; i++)
#pragma unroll
                for (int j = 0; j < 8; j++) acc[i][j] += a[i] * bb[j];
        }
        __syncthreads();
    }
#pragma unroll
    for (int i = 0; i < 8; i++) {
        size_t row = (size_t)(m0 + rg + i) * 1024;
#pragma unroll
        for (int j = 0; j < 8; j++) {
            g_QK[row + J0 + cg + j] = acc[i][j] + bias[j0 + cg + j];
        }
    }
}

// ---------------- kernel 2: l2norm Q,K in place; qg; partial G, partial ||qg||^2
// 64 tokens per block (3136 % 64 == 0, never crosses batch), one warp per token.
__global__ __launch_bounds__(256) void k_normalize(const float* __restrict__ w_g)
{
    __shared__ float s_wg[512];
    __shared__ float sG[8][512];
    __shared__ float sS[8];
    const int tid  = threadIdx.x;
    const int lane = tid & 31;
    const int warp = tid >> 5;
    for (int i = tid; i < 512; i += 256) s_wg[i] = w_g[i];
    __syncthreads();

    const int m0 = blockIdx.x * 64;

    float Gl[16];
#pragma unroll
    for (int u = 0; u < 16; u++) Gl[u] = 0.f;
    float ssl = 0.f;

    for (int t = warp; t < 64; t += 8) {
        size_t base = (size_t)(m0 + t) * 1024;
        // ---- Q ----
        float q[16];
        float ss = 0.f;
#pragma unroll
        for (int u = 0; u < 16; u++) { q[u] = g_QK[base + lane + 32 * u]; ss += q[u] * q[u]; }
#pragma unroll
        for (int o = 16; o > 0; o >>= 1) ss += __shfl_xor_sync(0xffffffff, ss, o);
        float inv = 1.f / fmaxf(sqrtf(ss), L2EPS);
        float qg = 0.f;
#pragma unroll
        for (int u = 0; u < 16; u++) {
            q[u] *= inv;
            g_QK[base + lane + 32 * u] = q[u];
            qg += q[u] * s_wg[lane + 32 * u];
        }
#pragma unroll
        for (int o = 16; o > 0; o >>= 1) qg += __shfl_xor_sync(0xffffffff, qg, o);
#pragma unroll
        for (int u = 0; u < 16; u++) Gl[u] += qg * q[u];
        ssl += qg * qg;
        // ---- K ----
        float kk[16]; float ssk = 0.f;
#pragma unroll
        for (int u = 0; u < 16; u++) { kk[u] = g_QK[base + 512 + lane + 32 * u]; ssk += kk[u] * kk[u]; }
#pragma unroll
        for (int o = 16; o > 0; o >>= 1) ssk += __shfl_xor_sync(0xffffffff, ssk, o);
        float invk = 1.f / fmaxf(sqrtf(ssk), L2EPS);
#pragma unroll
        for (int u = 0; u < 16; u++) g_QK[base + 512 + lane + 32 * u] = kk[u] * invk;
    }
#pragma unroll
    for (int u = 0; u < 16; u++) sG[warp][lane + 32 * u] = Gl[u];
    if (lane == 0) sS[warp] = ssl;
    __syncthreads();
    for (int j = tid; j < 512; j += 256) {
        float s = 0.f;
#pragma unroll
        for (int w2 = 0; w2 < 8; w2++) s += sG[w2][j];
        g_Gpart[blockIdx.x * 512 + j] = s;
    }
    if (tid == 0) {
        float s = 0.f;
        for (int w2 = 0; w2 < 8; w2++) s += sS[w2];
        g_sspart[blockIdx.x] = s;
    }
}

// ---------------- kernel 3: dyn = gelu(Q@wd1 + bd1) @ wd2 + bd2 --------------
// Fused: 32 token rows x full 512 cols per block, never materializes the
// [M,512] activation. TK=8.
__global__ __launch_bounds__(256) void k_dyn(
    const float* __restrict__ wd1, const float* __restrict__ bd1,
    const float* __restrict__ wd2, const float* __restrict__ bd2)
{
    __shared__ float As[8][32];
    __shared__ float Bs[8][512];
    __shared__ float s_b1[512];
    __shared__ float s_w2[512];
    const int tid = threadIdx.x;
    const int m0  = blockIdx.x * 32;
    for (int i = tid; i < 512; i += 256) { s_b1[i] = bd1[i]; s_w2[i] = wd2[i]; }

    const int lane = tid & 31;
    const int rg   = tid >> 5;        // 0..7 -> rows rg*4..rg*4+3
    float acc[4][16];
#pragma unroll
    for (int r = 0; r < 4; r++)
#pragma unroll
        for (int u = 0; u < 16; u++) acc[r][u] = 0.f;

    const int a_k = tid & 7;
    const int a_r = tid >> 3;         // 0..31
    __syncthreads();

    for (int kt = 0; kt < 512; kt += 8) {
        As[a_k][a_r] = g_QK[(size_t)(m0 + a_r) * 1024 + kt + a_k];
#pragma unroll
        for (int i = 0; i < 16; i++) {
            int e = tid + 256 * i;
            int j = e & 511;
            int k = e >> 9;
            Bs[k][j] = wd1[(size_t)(kt + k) * 512 + j];
        }
        __syncthreads();
#pragma unroll
        for (int k = 0; k < 8; k++) {
            float a0 = As[k][rg * 4 + 0], a1 = As[k][rg * 4 + 1];
            float a2 = As[k][rg * 4 + 2], a3 = As[k][rg * 4 + 3];
#pragma unroll
            for (int u = 0; u < 16; u++) {
                float b = Bs[k][lane + 32 * u];
                acc[0][u] += a0 * b; acc[1][u] += a1 * b;
                acc[2][u] += a2 * b; acc[3][u] += a3 * b;
            }
        }
        __syncthreads();
    }
#pragma unroll
    for (int r = 0; r < 4; r++) {
        float s = 0.f;
#pragma unroll
        for (int u = 0; u < 16; u++) {
            float z = acc[r][u] + s_b1[lane + 32 * u];
            s += gelu_f(z) * s_w2[lane + 32 * u];
        }
#pragma unroll
        for (int o = 16; o > 0; o >>= 1) s += __shfl_xor_sync(0xffffffff, s, o);
        if (lane == 0) g_dyn[m0 + rg * 4 + r] = s + bd2[0];
    }
}

// ---------------- kernel 4: per-batch finalize: G, softmax weights -----------
__global__ __launch_bounds__(256) void k_finalize()
{
    __shared__ float red[256];
    const int b   = blockIdx.x;
    const int tid = threadIdx.x;

    if (tid == 0) {
        float s = 0.f;
        for (int i = 0; i < 49; i++) s += g_sspart[b * 49 + i];
        red[0] = s;
    }
    __syncthreads();
    const float SCALE = 0.0625f;      // 256^-0.5
    float denom = fmaxf(SCALE * sqrtf(red[0]), L2EPS);
    float f = SCALE / denom;
    __syncthreads();

    for (int j = tid; j < 512; j += 256) {
        float s = 0.f;
        for (int i = 0; i < 49; i++) s += g_Gpart[(size_t)(b * 49 + i) * 512 + j];
        g_G[b * 512 + j] = f * s;
    }

    // softmax over tokens (deterministic fixed-order partials + tree)
    float mx = -1e30f;
    for (int n = tid; n < NTOK; n += 256) mx = fmaxf(mx, g_dyn[b * NTOK + n]);
    red[tid] = mx; __syncthreads();
    for (int o = 128; o > 0; o >>= 1) { if (tid < o) red[tid] = fmaxf(red[tid], red[tid + o]); __syncthreads(); }
    mx = red[0]; __syncthreads();

    float se = 0.f;
    for (int n = tid; n < NTOK; n += 256) se += expf(g_dyn[b * NTOK + n] - mx);
    red[tid] = se; __syncthreads();
    for (int o = 128; o > 0; o >>= 1) { if (tid < o) red[tid] += red[tid + o]; __syncthreads(); }
    float inv = 1.f / red[0];
    for (int n = tid; n < NTOK; n += 256)
        g_w[b * NTOK + n] = expf(g_dyn[b * NTOK + n] - mx) * inv;
}

// ---------------- kernel 5: out = gelu(w*G*K + Q) @ wf + bf ------------------
// Transposed tile: 256 output channels (rows) x 64 tokens (cols) so stores into
// [B, 256, H, W] hit 32B-contiguous token runs. 64-token tiles never cross batch.
__global__ __launch_bounds__(256) void k_out(
    const float* __restrict__ wf, const float* __restrict__ bf,
    float* __restrict__ out)
{
    __shared__ float At[8][256];     // wf^T tile: At[k][t]
    __shared__ float Ns[8][64];      // A'^T tile: Ns[k][n] = gelu(w*G*K + Q)
    __shared__ float Gs[512];
    __shared__ float s_bf[256];
    const int tid = threadIdx.x;
    const int m0  = blockIdx.x * 64;
    const int b   = m0 / NTOK;
    const int n0  = m0 - b * NTOK;

    for (int i = tid; i < 512; i += 256) Gs[i] = g_G[b * 512 + i];
    s_bf[tid] = bf[tid];

    const int rg = tid >> 3;          // 0..31 -> t rows rg*8..+7
    const int cg = tid & 7;           // token cols cg + 8*uu

    // A' build coords: k = tid&7, token rows tid>>3 and +32
    const int l_k = tid & 7;
    const int l_n = tid >> 3;
    const size_t row0 = (size_t)(m0 + l_n) * 1024;
    const size_t row1 = (size_t)(m0 + l_n + 32) * 1024;
    const float wn0 = g_w[m0 + l_n];
    const float wn1 = g_w[m0 + l_n + 32];

    float acc[8][8];
#pragma unroll
    for (int i = 0; i < 8; i++)
#pragma unroll
        for (int j = 0; j < 8; j++) acc[i][j] = 0.f;

    __syncthreads();

    for (int kt = 0; kt < 512; kt += 8) {
#pragma unroll
        for (int i = 0; i < 8; i++)
            At[i][tid] = wf[(size_t)(kt + i) * 256 + tid];
        {
            int c = kt + l_k;
            float g = Gs[c];
            float q0 = g_QK[row0 + c], kv0 = g_QK[row0 + 512 + c];
            float q1 = g_QK[row1 + c], kv1 = g_QK[row1 + 512 + c];
            Ns[l_k][l_n]      = gelu_f(wn0 * g * kv0 + q0);
            Ns[l_k][l_n + 32] = gelu_f(wn1 * g * kv1 + q1);
        }
        __syncthreads();
#pragma unroll
        for (int k = 0; k < 8; k++) {
            float a[8], bb[8];
#pragma unroll
            for (int i = 0; i < 8; i++) a[i] = At[k][rg * 8 + i];
#pragma unroll
            for (int j = 0; j < 8; j++) bb[j] = Ns[k][cg + 8 * j];
#pragma unroll
            for (int i = 0; i < 8; i++)
#pragma unroll
                for (int j = 0; j < 8; j++) acc[i][j] += a[i] * bb[j];
        }
        __syncthreads();
    }

#pragma unroll
    for (int i = 0; i < 8; i++) {
        int t = rg * 8 + i;
        float bias = s_bf[t];
        size_t base = ((size_t)b * 256 + t) * NTOK + n0;
#pragma unroll
        for (int j = 0; j < 8; j++) {
            out[base + cg + 8 * j] = acc[i][j] + bias;
        }
    }
}

// -----------------------------------------------------------------------------
extern "C" void kernel_launch(void* const* d_in, const int* in_sizes, int n_in,
                              void* d_out, int out_size)
{
    const float* x   = (const float*)d_in[0];
    const float* wq  = (const float*)d_in[1];
    const float* bq  = (const float*)d_in[2];
    const float* wk  = (const float*)d_in[3];
    const float* bk  = (const float*)d_in[4];
    const float* w_g = (const float*)d_in[5];
    const float* wd1 = (const float*)d_in[6];
    const float* bd1 = (const float*)d_in[7];
    const float* wd2 = (const float*)d_in[8];
    const float* bd2 = (const float*)d_in[9];
    const float* wf  = (const float*)d_in[10];
    const float* bf  = (const float*)d_in[11];
    float* out = (float*)d_out;

    k_gemm_qk<<<dim3(MTOT / 128, 8), 256>>>(x, wq, bq, wk, bk);
    k_normalize<<<NBLK64, 256>>>(w_g);
    k_dyn<<<MTOT / 32, 256>>>(wd1, bd1, wd2, bd2);
    k_finalize<<<BATCH, 256>>>();
    k_out<<<NBLK64, 256>>>(wf, bf, out);
}

// round 8
// speedup vs baseline: 1.0461x; 1.0461x over previous
#include <cuda_runtime.h>
#include <math.h>

#define BATCH 16
#define CCH   512
#define NTOK  3136
#define DD    512
#define TDOUT 256
#define MTOT  (BATCH*NTOK)     // 50176
#define NBLK64 (MTOT/64)       // 784
#define L2EPS 1e-12f

// ---------------- scratch (device globals; no runtime allocation) ------------
__device__ float g_QK[(size_t)MTOT * 1024];  // per token: [0:512)=Q, [512:1024)=K (pre-norm then normalized in place)
__device__ float g_Gpart[NBLK64 * 512];      // per-block partial of sum_n qg_n * Q_n
__device__ float g_sspart[NBLK64];           // per-block partial of sum qg^2
__device__ float g_dyn[MTOT];                // gating logits
__device__ float g_w[MTOT];                  // softmax weights
__device__ float g_G[BATCH * DD];            // global query (already scaled by 1/||qg||)

__device__ __forceinline__ float gelu_f(float x) {
    // exact GELU (approximate=False)
    return 0.5f * x * (1.0f + erff(x * 0.70710678118654752440f));
}

// ---------------- kernel 1: [Q|K] = xt @ [wq|wk] + [bq|bk] -------------------
// A is x in [b, c, n] layout -> xt[m=(b,n), c] = x[b*C*N + c*N + n]
// 128x128x8 fp32 tile, 256 threads, 8x8 per thread.
__global__ __launch_bounds__(256) void k_gemm_qk(
    const float* __restrict__ x,
    const float* __restrict__ wq, const float* __restrict__ bq,
    const float* __restrict__ wk, const float* __restrict__ bk)
{
    __shared__ float As[8][128];
    __shared__ float Bs[8][128];
    const int tid = threadIdx.x;
    const int m0 = blockIdx.x * 128;
    const int J0 = blockIdx.y * 128;          // 0..1023

    const float* wmat; const float* bias; int j0;
    if (J0 < 512) { wmat = wq; bias = bq; j0 = J0; }
    else          { wmat = wk; bias = bk; j0 = J0 - 512; }

    // A loads: each thread owns one fixed row of the tile
    const int a_m  = tid & 127;
    const int a_k0 = tid >> 7;                // 0/1, k = a_k0 + 2*i
    const int gm = m0 + a_m;
    const int b_idx = gm / NTOK;
    const int n_idx = gm - b_idx * NTOK;
    const float* xrow = x + (size_t)b_idx * CCH * NTOK + n_idx;

    // B loads: each thread owns one fixed column
    const int bj  = tid & 127;
    const int bk0 = tid >> 7;

    float acc[8][8];
#pragma unroll
    for (int i = 0; i < 8; i++)
#pragma unroll
        for (int j = 0; j < 8; j++) acc[i][j] = 0.f;

    const int rg = (tid >> 4) * 8;
    const int cg = (tid & 15) * 8;

    for (int kt = 0; kt < CCH; kt += 8) {
#pragma unroll
        for (int i = 0; i < 4; i++) {
            int k = a_k0 + 2 * i;
            As[k][a_m] = xrow[(size_t)(kt + k) * NTOK];
        }
#pragma unroll
        for (int i = 0; i < 4; i++) {
            int k = bk0 + 2 * i;
            Bs[k][bj] = wmat[(size_t)(kt + k) * 512 + j0 + bj];
        }
        __syncthreads();
#pragma unroll
        for (int k = 0; k < 8; k++) {
            float a[8], bb[8];
#pragma unroll
            for (int i = 0; i < 8; i++) a[i] = As[k][rg + i];
#pragma unroll
            for (int j = 0; j < 8; j++) bb[j] = Bs[k][cg + j];
#pragma unroll
            for (int i = 0; i < 8; i++)
#pragma unroll
                for (int j = 0; j < 8; j++) acc[i][j] += a[i] * bb[j];
        }
        __syncthreads();
    }
#pragma unroll
    for (int i = 0; i < 8; i++) {
        size_t row = (size_t)(m0 + rg + i) * 1024;
#pragma unroll
        for (int j = 0; j < 8; j++) {
            g_QK[row + J0 + cg + j] = acc[i][j] + bias[j0 + cg + j];
        }
    }
}

// ---------------- kernel 2: l2norm Q,K in place; qg; partial G, partial ||qg||^2
// 64 tokens per block (3136 % 64 == 0, never crosses batch), one warp per token.
__global__ __launch_bounds__(256) void k_normalize(const float* __restrict__ w_g)
{
    __shared__ float s_wg[512];
    __shared__ float sG[8][512];
    __shared__ float sS[8];
    const int tid  = threadIdx.x;
    const int lane = tid & 31;
    const int warp = tid >> 5;
    for (int i = tid; i < 512; i += 256) s_wg[i] = w_g[i];
    __syncthreads();

    const int m0 = blockIdx.x * 64;

    float Gl[16];
#pragma unroll
    for (int u = 0; u < 16; u++) Gl[u] = 0.f;
    float ssl = 0.f;

    for (int t = warp; t < 64; t += 8) {
        size_t base = (size_t)(m0 + t) * 1024;
        // ---- Q ----
        float q[16];
        float ss = 0.f;
#pragma unroll
        for (int u = 0; u < 16; u++) { q[u] = g_QK[base + lane + 32 * u]; ss += q[u] * q[u]; }
#pragma unroll
        for (int o = 16; o > 0; o >>= 1) ss += __shfl_xor_sync(0xffffffff, ss, o);
        float inv = 1.f / fmaxf(sqrtf(ss), L2EPS);
        float qg = 0.f;
#pragma unroll
        for (int u = 0; u < 16; u++) {
            q[u] *= inv;
            g_QK[base + lane + 32 * u] = q[u];
            qg += q[u] * s_wg[lane + 32 * u];
        }
#pragma unroll
        for (int o = 16; o > 0; o >>= 1) qg += __shfl_xor_sync(0xffffffff, qg, o);
#pragma unroll
        for (int u = 0; u < 16; u++) Gl[u] += qg * q[u];
        ssl += qg * qg;
        // ---- K ----
        float kk[16]; float ssk = 0.f;
#pragma unroll
        for (int u = 0; u < 16; u++) { kk[u] = g_QK[base + 512 + lane + 32 * u]; ssk += kk[u] * kk[u]; }
#pragma unroll
        for (int o = 16; o > 0; o >>= 1) ssk += __shfl_xor_sync(0xffffffff, ssk, o);
        float invk = 1.f / fmaxf(sqrtf(ssk), L2EPS);
#pragma unroll
        for (int u = 0; u < 16; u++) g_QK[base + 512 + lane + 32 * u] = kk[u] * invk;
    }
#pragma unroll
    for (int u = 0; u < 16; u++) sG[warp][lane + 32 * u] = Gl[u];
    if (lane == 0) sS[warp] = ssl;
    __syncthreads();
    for (int j = tid; j < 512; j += 256) {
        float s = 0.f;
#pragma unroll
        for (int w2 = 0; w2 < 8; w2++) s += sG[w2][j];
        g_Gpart[blockIdx.x * 512 + j] = s;
    }
    if (tid == 0) {
        float s = 0.f;
        for (int w2 = 0; w2 < 8; w2++) s += sS[w2];
        g_sspart[blockIdx.x] = s;
    }
}

// ---------------- kernel 3: dyn = gelu(Q@wd1 + bd1) @ wd2 + bd2 --------------
// Fused: 32 token rows x full 512 cols per block, never materializes the
// [M,512] activation. TK=8.
__global__ __launch_bounds__(256) void k_dyn(
    const float* __restrict__ wd1, const float* __restrict__ bd1,
    const float* __restrict__ wd2, const float* __restrict__ bd2)
{
    __shared__ float As[8][32];
    __shared__ float Bs[8][512];
    __shared__ float s_b1[512];
    __shared__ float s_w2[512];
    const int tid = threadIdx.x;
    const int m0  = blockIdx.x * 32;
    for (int i = tid; i < 512; i += 256) { s_b1[i] = bd1[i]; s_w2[i] = wd2[i]; }

    const int lane = tid & 31;
    const int rg   = tid >> 5;        // 0..7 -> rows rg*4..rg*4+3
    float acc[4][16];
#pragma unroll
    for (int r = 0; r < 4; r++)
#pragma unroll
        for (int u = 0; u < 16; u++) acc[r][u] = 0.f;

    const int a_k = tid & 7;
    const int a_r = tid >> 3;         // 0..31
    __syncthreads();

    for (int kt = 0; kt < 512; kt += 8) {
        As[a_k][a_r] = g_QK[(size_t)(m0 + a_r) * 1024 + kt + a_k];
#pragma unroll
        for (int i = 0; i < 16; i++) {
            int e = tid + 256 * i;
            int j = e & 511;
            int k = e >> 9;
            Bs[k][j] = wd1[(size_t)(kt + k) * 512 + j];
        }
        __syncthreads();
#pragma unroll
        for (int k = 0; k < 8; k++) {
            float a0 = As[k][rg * 4 + 0], a1 = As[k][rg * 4 + 1];
            float a2 = As[k][rg * 4 + 2], a3 = As[k][rg * 4 + 3];
#pragma unroll
            for (int u = 0; u < 16; u++) {
                float b = Bs[k][lane + 32 * u];
                acc[0][u] += a0 * b; acc[1][u] += a1 * b;
                acc[2][u] += a2 * b; acc[3][u] += a3 * b;
            }
        }
        __syncthreads();
    }
#pragma unroll
    for (int r = 0; r < 4; r++) {
        float s = 0.f;
#pragma unroll
        for (int u = 0; u < 16; u++) {
            float z = acc[r][u] + s_b1[lane + 32 * u];
            s += gelu_f(z) * s_w2[lane + 32 * u];
        }
#pragma unroll
        for (int o = 16; o > 0; o >>= 1) s += __shfl_xor_sync(0xffffffff, s, o);
        if (lane == 0) g_dyn[m0 + rg * 4 + r] = s + bd2[0];
    }
}

// ---------------- kernel 4: per-batch finalize: G, softmax weights -----------
__global__ __launch_bounds__(256) void k_finalize()
{
    __shared__ float red[256];
    const int b   = blockIdx.x;
    const int tid = threadIdx.x;

    if (tid == 0) {
        float s = 0.f;
        for (int i = 0; i < 49; i++) s += g_sspart[b * 49 + i];
        red[0] = s;
    }
    __syncthreads();
    const float SCALE = 0.0625f;      // 256^-0.5
    float denom = fmaxf(SCALE * sqrtf(red[0]), L2EPS);
    float f = SCALE / denom;
    __syncthreads();

    for (int j = tid; j < 512; j += 256) {
        float s = 0.f;
        for (int i = 0; i < 49; i++) s += g_Gpart[(size_t)(b * 49 + i) * 512 + j];
        g_G[b * 512 + j] = f * s;
    }

    // softmax over tokens (deterministic fixed-order partials + tree)
    float mx = -1e30f;
    for (int n = tid; n < NTOK; n += 256) mx = fmaxf(mx, g_dyn[b * NTOK + n]);
    red[tid] = mx; __syncthreads();
    for (int o = 128; o > 0; o >>= 1) { if (tid < o) red[tid] = fmaxf(red[tid], red[tid + o]); __syncthreads(); }
    mx = red[0]; __syncthreads();

    float se = 0.f;
    for (int n = tid; n < NTOK; n += 256) se += expf(g_dyn[b * NTOK + n] - mx);
    red[tid] = se; __syncthreads();
    for (int o = 128; o > 0; o >>= 1) { if (tid < o) red[tid] += red[tid + o]; __syncthreads(); }
    float inv = 1.f / red[0];
    for (int n = tid; n < NTOK; n += 256)
        g_w[b * NTOK + n] = expf(g_dyn[b * NTOK + n] - mx) * inv;
}

// ---------------- kernel 5: out = gelu(w*G*K + Q) @ wf + bf ------------------
// Transposed tile: 256 output channels (rows) x 64 tokens (cols) so stores into
// [B, 256, H, W] hit 32B-contiguous token runs. 64-token tiles never cross batch.
__global__ __launch_bounds__(256) void k_out(
    const float* __restrict__ wf, const float* __restrict__ bf,
    float* __restrict__ out)
{
    __shared__ float At[8][256];     // wf^T tile: At[k][t]
    __shared__ float Ns[8][64];      // A'^T tile: Ns[k][n] = gelu(w*G*K + Q)
    __shared__ float Gs[512];
    __shared__ float s_bf[256];
    const int tid = threadIdx.x;
    const int m0  = blockIdx.x * 64;
    const int b   = m0 / NTOK;
    const int n0  = m0 - b * NTOK;

    for (int i = tid; i < 512; i += 256) Gs[i] = g_G[b * 512 + i];
    s_bf[tid] = bf[tid];

    const int rg = tid >> 3;          // 0..31 -> t rows rg*8..+7
    const int cg = tid & 7;           // token cols cg + 8*uu

    // A' build coords: k = tid&7, token rows tid>>3 and +32
    const int l_k = tid & 7;
    const int l_n = tid >> 3;
    const size_t row0 = (size_t)(m0 + l_n) * 1024;
    const size_t row1 = (size_t)(m0 + l_n + 32) * 1024;
    const float wn0 = g_w[m0 + l_n];
    const float wn1 = g_w[m0 + l_n + 32];

    float acc[8][8];
#pragma unroll
    for (int i = 0; i < 8; i++)
#pragma unroll
        for (int j = 0; j < 8; j++) acc[i][j] = 0.f;

    __syncthreads();

    for (int kt = 0; kt < 512; kt += 8) {
#pragma unroll
        for (int i = 0; i < 8; i++)
            At[i][tid] = wf[(size_t)(kt + i) * 256 + tid];
        {
            int c = kt + l_k;
            float g = Gs[c];
            float q0 = g_QK[row0 + c], kv0 = g_QK[row0 + 512 + c];
            float q1 = g_QK[row1 + c], kv1 = g_QK[row1 + 512 + c];
            Ns[l_k][l_n]      = gelu_f(wn0 * g * kv0 + q0);
            Ns[l_k][l_n + 32] = gelu_f(wn1 * g * kv1 + q1);
        }
        __syncthreads();
#pragma unroll
        for (int k = 0; k < 8; k++) {
            float a[8], bb[8];
#pragma unroll
            for (int i = 0; i < 8; i++) a[i] = At[k][rg * 8 + i];
#pragma unroll
            for (int j = 0; j < 8; j++) bb[j] = Ns[k][cg + 8 * j];
#pragma unroll
            for (int i = 0; i < 8; i++)
#pragma unroll
                for (int j = 0; j < 8; j++) acc[i][j] += a[i] * bb[j];
        }
        __syncthreads();
    }

#pragma unroll
    for (int i = 0; i < 8; i++) {
        int t = rg * 8 + i;
        float bias = s_bf[t];
        size_t base = ((size_t)b * 256 + t) * NTOK + n0;
#pragma unroll
        for (int j = 0; j < 8; j++) {
            out[base + cg + 8 * j] = acc[i][j] + bias;
        }
    }
}

// -----------------------------------------------------------------------------
extern "C" void kernel_launch(void* const* d_in, const int* in_sizes, int n_in,
                              void* d_out, int out_size)
{
    const float* x   = (const float*)d_in[0];
    const float* wq  = (const float*)d_in[1];
    const float* bq  = (const float*)d_in[2];
    const float* wk  = (const float*)d_in[3];
    const float* bk  = (const float*)d_in[4];
    const float* w_g = (const float*)d_in[5];
    const float* wd1 = (const float*)d_in[6];
    const float* bd1 = (const float*)d_in[7];
    const float* wd2 = (const float*)d_in[8];
    const float* bd2 = (const float*)d_in[9];
    const float* wf  = (const float*)d_in[10];
    const float* bf  = (const float*)d_in[11];
    float* out = (float*)d_out;

    k_gemm_qk<<<dim3(MTOT / 128, 8), 256>>>(x, wq, bq, wk, bk);
    k_normalize<<<NBLK64, 256>>>(w_g);
    k_dyn<<<MTOT / 32, 256>>>(wd1, bd1, wd2, bd2);
    k_finalize<<<BATCH, 256>>>();
    k_out<<<NBLK64, 256>>>(wf, bf, out);
}

// round 9
// speedup vs baseline: 1.0475x; 1.0014x over previous
#include <cuda_runtime.h>
#include <math.h>

#define BATCH 16
#define CCH   512
#define NTOK  3136
#define DD    512
#define TDOUT 256
#define MTOT  (BATCH*NTOK)     // 50176
#define NBLK64 (MTOT/64)       // 784
#define L2EPS 1e-12f

// ---------------- scratch (device globals; no runtime allocation) ------------
__device__ float g_QK[(size_t)MTOT * 1024];  // per token: [0:512)=Q, [512:1024)=K (pre-norm then normalized in place)
__device__ float g_Gpart[NBLK64 * 512];      // per-block partial of sum_n qg_n * Q_n
__device__ float g_sspart[NBLK64];           // per-block partial of sum qg^2
__device__ float g_dyn[MTOT];                // gating logits
__device__ float g_w[MTOT];                  // softmax weights
__device__ float g_G[BATCH * DD];            // global query (already scaled by 1/||qg||)

__device__ __forceinline__ float gelu_f(float x) {
    // exact GELU (approximate=False)
    return 0.5f * x * (1.0f + erff(x * 0.70710678118654752440f));
}

// ---------------- kernel 1: [Q|K] = xt @ [wq|wk] + [bq|bk] -------------------
// A is x in [b, c, n] layout -> xt[m=(b,n), c] = x[b*C*N + c*N + n]
// 128x128x8 fp32 tile, 256 threads, 8x8 per thread.
__global__ __launch_bounds__(256) void k_gemm_qk(
    const float* __restrict__ x,
    const float* __restrict__ wq, const float* __restrict__ bq,
    const float* __restrict__ wk, const float* __restrict__ bk)
{
    __shared__ float As[8][128];
    __shared__ float Bs[8][128];
    const int tid = threadIdx.x;
    const int m0 = blockIdx.x * 128;
    const int J0 = blockIdx.y * 128;          // 0..1023

    const float* wmat; const float* bias; int j0;
    if (J0 < 512) { wmat = wq; bias = bq; j0 = J0; }
    else          { wmat = wk; bias = bk; j0 = J0 - 512; }

    // A loads: each thread owns one fixed row of the tile
    const int a_m  = tid & 127;
    const int a_k0 = tid >> 7;                // 0/1, k = a_k0 + 2*i
    const int gm = m0 + a_m;
    const int b_idx = gm / NTOK;
    const int n_idx = gm - b_idx * NTOK;
    const float* xrow = x + (size_t)b_idx * CCH * NTOK + n_idx;

    // B loads: each thread owns one fixed column
    const int bj  = tid & 127;
    const int bk0 = tid >> 7;

    float acc[8][8];
#pragma unroll
    for (int i = 0; i < 8; i++)
#pragma unroll
        for (int j = 0; j < 8; j++) acc[i][j] = 0.f;

    const int rg = (tid >> 4) * 8;
    const int cg = (tid & 15) * 8;

    for (int kt = 0; kt < CCH; kt += 8) {
#pragma unroll
        for (int i = 0; i < 4; i++) {
            int k = a_k0 + 2 * i;
            As[k][a_m] = xrow[(size_t)(kt + k) * NTOK];
        }
#pragma unroll
        for (int i = 0; i < 4; i++) {
            int k = bk0 + 2 * i;
            Bs[k][bj] = wmat[(size_t)(kt + k) * 512 + j0 + bj];
        }
        __syncthreads();
#pragma unroll
        for (int k = 0; k < 8; k++) {
            float a[8], bb[8];
#pragma unroll
            for (int i = 0; i < 8; i++) a[i] = As[k][rg + i];
#pragma unroll
            for (int j = 0; j < 8; j++) bb[j] = Bs[k][cg + j];
#pragma unroll
            for (int i = 0; i < 8; i++)
#pragma unroll
                for (int j = 0; j < 8; j++) acc[i][j] += a[i] * bb[j];
        }
        __syncthreads();
    }
#pragma unroll
    for (int i = 0; i < 8; i++) {
        size_t row = (size_t)(m0 + rg + i) * 1024;
#pragma unroll
        for (int j = 0; j < 8; j++) {
            g_QK[row + J0 + cg + j] = acc[i][j] + bias[j0 + cg + j];
        }
    }
}

// ---------------- kernel 2: l2norm Q,K in place; qg; partial G, partial ||qg||^2
// 64 tokens per block (3136 % 64 == 0, never crosses batch), one warp per token.
__global__ __launch_bounds__(256) void k_normalize(const float* __restrict__ w_g)
{
    __shared__ float s_wg[512];
    __shared__ float sG[8][512];
    __shared__ float sS[8];
    const int tid  = threadIdx.x;
    const int lane = tid & 31;
    const int warp = tid >> 5;
    for (int i = tid; i < 512; i += 256) s_wg[i] = w_g[i];
    __syncthreads();

    const int m0 = blockIdx.x * 64;

    float Gl[16];
#pragma unroll
    for (int u = 0; u < 16; u++) Gl[u] = 0.f;
    float ssl = 0.f;

    for (int t = warp; t < 64; t += 8) {
        size_t base = (size_t)(m0 + t) * 1024;
        // ---- Q ----
        float q[16];
        float ss = 0.f;
#pragma unroll
        for (int u = 0; u < 16; u++) { q[u] = g_QK[base + lane + 32 * u]; ss += q[u] * q[u]; }
#pragma unroll
        for (int o = 16; o > 0; o >>= 1) ss += __shfl_xor_sync(0xffffffff, ss, o);
        float inv = 1.f / fmaxf(sqrtf(ss), L2EPS);
        float qg = 0.f;
#pragma unroll
        for (int u = 0; u < 16; u++) {
            q[u] *= inv;
            g_QK[base + lane + 32 * u] = q[u];
            qg += q[u] * s_wg[lane + 32 * u];
        }
#pragma unroll
        for (int o = 16; o > 0; o >>= 1) qg += __shfl_xor_sync(0xffffffff, qg, o);
#pragma unroll
        for (int u = 0; u < 16; u++) Gl[u] += qg * q[u];
        ssl += qg * qg;
        // ---- K ----
        float kk[16]; float ssk = 0.f;
#pragma unroll
        for (int u = 0; u < 16; u++) { kk[u] = g_QK[base + 512 + lane + 32 * u]; ssk += kk[u] * kk[u]; }
#pragma unroll
        for (int o = 16; o > 0; o >>= 1) ssk += __shfl_xor_sync(0xffffffff, ssk, o);
        float invk = 1.f / fmaxf(sqrtf(ssk), L2EPS);
#pragma unroll
        for (int u = 0; u < 16; u++) g_QK[base + 512 + lane + 32 * u] = kk[u] * invk;
    }
#pragma unroll
    for (int u = 0; u < 16; u++) sG[warp][lane + 32 * u] = Gl[u];
    if (lane == 0) sS[warp] = ssl;
    __syncthreads();
    for (int j = tid; j < 512; j += 256) {
        float s = 0.f;
#pragma unroll
        for (int w2 = 0; w2 < 8; w2++) s += sG[w2][j];
        g_Gpart[blockIdx.x * 512 + j] = s;
    }
    if (tid == 0) {
        float s = 0.f;
        for (int w2 = 0; w2 < 8; w2++) s += sS[w2];
        g_sspart[blockIdx.x] = s;
    }
}

// ---------------- kernel 3: dyn = gelu(Q@wd1 + bd1) @ wd2 + bd2 --------------
// Fused: 32 token rows x full 512 cols per block, never materializes the
// [M,512] activation. TK=8.
__global__ __launch_bounds__(256) void k_dyn(
    const float* __restrict__ wd1, const float* __restrict__ bd1,
    const float* __restrict__ wd2, const float* __restrict__ bd2)
{
    __shared__ float As[8][32];
    __shared__ float Bs[8][512];
    __shared__ float s_b1[512];
    __shared__ float s_w2[512];
    const int tid = threadIdx.x;
    const int m0  = blockIdx.x * 32;
    for (int i = tid; i < 512; i += 256) { s_b1[i] = bd1[i]; s_w2[i] = wd2[i]; }

    const int lane = tid & 31;
    const int rg   = tid >> 5;        // 0..7 -> rows rg*4..rg*4+3
    float acc[4][16];
#pragma unroll
    for (int r = 0; r < 4; r++)
#pragma unroll
        for (int u = 0; u < 16; u++) acc[r][u] = 0.f;

    const int a_k = tid & 7;
    const int a_r = tid >> 3;         // 0..31
    __syncthreads();

    for (int kt = 0; kt < 512; kt += 8) {
        As[a_k][a_r] = g_QK[(size_t)(m0 + a_r) * 1024 + kt + a_k];
#pragma unroll
        for (int i = 0; i < 16; i++) {
            int e = tid + 256 * i;
            int j = e & 511;
            int k = e >> 9;
            Bs[k][j] = wd1[(size_t)(kt + k) * 512 + j];
        }
        __syncthreads();
#pragma unroll
        for (int k = 0; k < 8; k++) {
            float a0 = As[k][rg * 4 + 0], a1 = As[k][rg * 4 + 1];
            float a2 = As[k][rg * 4 + 2], a3 = As[k][rg * 4 + 3];
#pragma unroll
            for (int u = 0; u < 16; u++) {
                float b = Bs[k][lane + 32 * u];
                acc[0][u] += a0 * b; acc[1][u] += a1 * b;
                acc[2][u] += a2 * b; acc[3][u] += a3 * b;
            }
        }
        __syncthreads();
    }
#pragma unroll
    for (int r = 0; r < 4; r++) {
        float s = 0.f;
#pragma unroll
        for (int u = 0; u < 16; u++) {
            float z = acc[r][u] + s_b1[lane + 32 * u];
            s += gelu_f(z) * s_w2[lane + 32 * u];
        }
#pragma unroll
        for (int o = 16; o > 0; o >>= 1) s += __shfl_xor_sync(0xffffffff, s, o);
        if (lane == 0) g_dyn[m0 + rg * 4 + r] = s + bd2[0];
    }
}

// ---------------- kernel 4: per-batch finalize: G, softmax weights -----------
__global__ __launch_bounds__(256) void k_finalize()
{
    __shared__ float red[256];
    const int b   = blockIdx.x;
    const int tid = threadIdx.x;

    if (tid == 0) {
        float s = 0.f;
        for (int i = 0; i < 49; i++) s += g_sspart[b * 49 + i];
        red[0] = s;
    }
    __syncthreads();
    const float SCALE = 0.0625f;      // 256^-0.5
    float denom = fmaxf(SCALE * sqrtf(red[0]), L2EPS);
    float f = SCALE / denom;
    __syncthreads();

    for (int j = tid; j < 512; j += 256) {
        float s = 0.f;
        for (int i = 0; i < 49; i++) s += g_Gpart[(size_t)(b * 49 + i) * 512 + j];
        g_G[b * 512 + j] = f * s;
    }

    // softmax over tokens (deterministic fixed-order partials + tree)
    float mx = -1e30f;
    for (int n = tid; n < NTOK; n += 256) mx = fmaxf(mx, g_dyn[b * NTOK + n]);
    red[tid] = mx; __syncthreads();
    for (int o = 128; o > 0; o >>= 1) { if (tid < o) red[tid] = fmaxf(red[tid], red[tid + o]); __syncthreads(); }
    mx = red[0]; __syncthreads();

    float se = 0.f;
    for (int n = tid; n < NTOK; n += 256) se += expf(g_dyn[b * NTOK + n] - mx);
    red[tid] = se; __syncthreads();
    for (int o = 128; o > 0; o >>= 1) { if (tid < o) red[tid] += red[tid + o]; __syncthreads(); }
    float inv = 1.f / red[0];
    for (int n = tid; n < NTOK; n += 256)
        g_w[b * NTOK + n] = expf(g_dyn[b * NTOK + n] - mx) * inv;
}

// ---------------- kernel 5: out = gelu(w*G*K + Q) @ wf + bf ------------------
// Transposed tile: 256 output channels (rows) x 64 tokens (cols) so stores into
// [B, 256, H, W] hit 32B-contiguous token runs. 64-token tiles never cross batch.
__global__ __launch_bounds__(256) void k_out(
    const float* __restrict__ wf, const float* __restrict__ bf,
    float* __restrict__ out)
{
    __shared__ float At[8][256];     // wf^T tile: At[k][t]
    __shared__ float Ns[8][64];      // A'^T tile: Ns[k][n] = gelu(w*G*K + Q)
    __shared__ float Gs[512];
    __shared__ float s_bf[256];
    const int tid = threadIdx.x;
    const int m0  = blockIdx.x * 64;
    const int b   = m0 / NTOK;
    const int n0  = m0 - b * NTOK;

    for (int i = tid; i < 512; i += 256) Gs[i] = g_G[b * 512 + i];
    s_bf[tid] = bf[tid];

    const int rg = tid >> 3;          // 0..31 -> t rows rg*8..+7
    const int cg = tid & 7;           // token cols cg + 8*uu

    // A' build coords: k = tid&7, token rows tid>>3 and +32
    const int l_k = tid & 7;
    const int l_n = tid >> 3;
    const size_t row0 = (size_t)(m0 + l_n) * 1024;
    const size_t row1 = (size_t)(m0 + l_n + 32) * 1024;
    const float wn0 = g_w[m0 + l_n];
    const float wn1 = g_w[m0 + l_n + 32];

    float acc[8][8];
#pragma unroll
    for (int i = 0; i < 8; i++)
#pragma unroll
        for (int j = 0; j < 8; j++) acc[i][j] = 0.f;

    __syncthreads();

    for (int kt = 0; kt < 512; kt += 8) {
#pragma unroll
        for (int i = 0; i < 8; i++)
            At[i][tid] = wf[(size_t)(kt + i) * 256 + tid];
        {
            int c = kt + l_k;
            float g = Gs[c];
            float q0 = g_QK[row0 + c], kv0 = g_QK[row0 + 512 + c];
            float q1 = g_QK[row1 + c], kv1 = g_QK[row1 + 512 + c];
            Ns[l_k][l_n]      = gelu_f(wn0 * g * kv0 + q0);
            Ns[l_k][l_n + 32] = gelu_f(wn1 * g * kv1 + q1);
        }
        __syncthreads();
#pragma unroll
        for (int k = 0; k < 8; k++) {
            float a[8], bb[8];
#pragma unroll
            for (int i = 0; i < 8; i++) a[i] = At[k][rg * 8 + i];
#pragma unroll
            for (int j = 0; j < 8; j++) bb[j] = Ns[k][cg + 8 * j];
#pragma unroll
            for (int i = 0; i < 8; i++)
#pragma unroll
                for (int j = 0; j < 8; j++) acc[i][j] += a[i] * bb[j];
        }
        __syncthreads();
    }

#pragma unroll
    for (int i = 0; i < 8; i++) {
        int t = rg * 8 + i;
        float bias = s_bf[t];
        size_t base = ((size_t)b * 256 + t) * NTOK + n0;
#pragma unroll
        for (int j = 0; j < 8; j++) {
            out[base + cg + 8 * j] = acc[i][j] + bias;
        }
    }
}

// -----------------------------------------------------------------------------
extern "C" void kernel_launch(void* const* d_in, const int* in_sizes, int n_in,
                              void* d_out, int out_size)
{
    const float* x   = (const float*)d_in[0];
    const float* wq  = (const float*)d_in[1];
    const float* bq  = (const float*)d_in[2];
    const float* wk  = (const float*)d_in[3];
    const float* bk  = (const float*)d_in[4];
    const float* w_g = (const float*)d_in[5];
    const float* wd1 = (const float*)d_in[6];
    const float* bd1 = (const float*)d_in[7];
    const float* wd2 = (const float*)d_in[8];
    const float* bd2 = (const float*)d_in[9];
    const float* wf  = (const float*)d_in[10];
    const float* bf  = (const float*)d_in[11];
    float* out = (float*)d_out;

    k_gemm_qk<<<dim3(MTOT / 128, 8), 256>>>(x, wq, bq, wk, bk);
    k_normalize<<<NBLK64, 256>>>(w_g);
    k_dyn<<<MTOT / 32, 256>>>(wd1, bd1, wd2, bd2);
    k_finalize<<<BATCH, 256>>>();
    k_out<<<NBLK64, 256>>>(wf, bf, out);
}